// round 2
// baseline (speedup 1.0000x reference)
#include <cuda_runtime.h>
#include <cstdint>

#define NN 8192
#define FI 256

// scratch for x1 = (adj @ x) / deg   (8192 x 256 fp32 = 8 MB)
__device__ float g_x1[NN * FI];

typedef unsigned long long u64;

// packed f32x2 FMA (Blackwell-only; 2 fp32 FMAs per instruction)
__device__ __forceinline__ void ffma2(u64 &d, u64 a, u64 b) {
    asm("fma.rn.f32x2 %0, %1, %2, %0;" : "+l"(d) : "l"(a), "l"(b));
}
__device__ __forceinline__ u64 dup2(float v) {
    u64 r; asm("mov.b64 %0, {%1, %2};" : "=l"(r) : "f"(v), "f"(v)); return r;
}
__device__ __forceinline__ float2 unpk(u64 v) {
    float2 r; asm("mov.b64 {%0, %1}, %2;" : "=f"(r.x), "=f"(r.y) : "l"(v)); return r;
}

// ---------------------------------------------------------------------------
// Kernel 1: x1[m, f] = (sum_j adj[m,j] * x[j,f]) / deg[m]
// Block tile: 128 (m) x 64 (f), K-chunks of 32.  256 threads, 8x4 micro-tile,
// f-dimension packed as f32x2.  deg computed from the resident adj smem tile.
// ---------------------------------------------------------------------------
__global__ void __launch_bounds__(256, 2)
agg_kernel(const int* __restrict__ adj, const float* __restrict__ x) {
    __shared__ float sA[128][36];   // adj tile as float, padded
    __shared__ float sX[32][68];    // x tile, padded
    __shared__ float sDeg[128];

    const int tid = threadIdx.x;
    const int tx = tid & 15, ty = tid >> 4;
    const int m0 = blockIdx.y * 128;
    const int f0 = blockIdx.x * 64;

    u64 acc[8][2];
#pragma unroll
    for (int r = 0; r < 8; ++r) { acc[r][0] = 0ull; acc[r][1] = 0ull; }
    float degAcc = 0.f;

    for (int k0 = 0; k0 < NN; k0 += 32) {
        __syncthreads();
        // load adj tile 128x32 (coalesced int4, convert to 0/1 float)
#pragma unroll
        for (int p = 0; p < 4; ++p) {
            int id = tid + p * 256;
            int row = id >> 3, q = id & 7;
            int4 v = *(const int4*)(adj + (size_t)(m0 + row) * NN + k0 + q * 4);
            float4 f;
            f.x = (v.x == 1) ? 1.f : 0.f;
            f.y = (v.y == 1) ? 1.f : 0.f;
            f.z = (v.z == 1) ? 1.f : 0.f;
            f.w = (v.w == 1) ? 1.f : 0.f;
            *(float4*)&sA[row][q * 4] = f;
        }
        // load x tile 32x64 (coalesced float4)
#pragma unroll
        for (int p = 0; p < 2; ++p) {
            int id = tid + p * 256;
            int kk = id >> 4, c4 = id & 15;
            *(float4*)&sX[kk][c4 * 4] =
                *(const float4*)(x + (size_t)(k0 + kk) * FI + f0 + c4 * 4);
        }
        __syncthreads();

        // per-row degree from the resident tile
        if (tid < 128) {
            float d = 0.f;
#pragma unroll
            for (int kk = 0; kk < 32; ++kk) d += sA[tid][kk];
            degAcc += d;
        }

        // 8x4 micro-tile, f packed into f32x2, two k-steps per iter
#pragma unroll
        for (int kk = 0; kk < 32; kk += 2) {
            ulonglong2 bA = *(ulonglong2*)&sX[kk][tx * 4];
            ulonglong2 bB = *(ulonglong2*)&sX[kk + 1][tx * 4];
#pragma unroll
            for (int r = 0; r < 8; ++r) {
                float2 a = *(float2*)&sA[ty * 8 + r][kk];
                u64 a0 = dup2(a.x), a1 = dup2(a.y);
                ffma2(acc[r][0], a0, bA.x);
                ffma2(acc[r][1], a0, bA.y);
                ffma2(acc[r][0], a1, bB.x);
                ffma2(acc[r][1], a1, bB.y);
            }
        }
    }

    if (tid < 128) sDeg[tid] = degAcc;
    __syncthreads();

#pragma unroll
    for (int r = 0; r < 8; ++r) {
        int row = ty * 8 + r;
        float inv = 1.0f / sDeg[row];
        float2 lo = unpk(acc[r][0]), hi = unpk(acc[r][1]);
        float4 o;
        o.x = lo.x * inv; o.y = lo.y * inv;
        o.z = hi.x * inv; o.w = hi.y * inv;
        *(float4*)(g_x1 + (size_t)(m0 + row) * FI + f0 + tx * 4) = o;
    }
}

// ---------------------------------------------------------------------------
// Kernel 2: out[k, n, o] = sum_f [x1|x][n, f] * W[k, f, o] + bias[o]
// Viewed as GEMM: M=8192, K=512 (x1 rows then x rows), 12 column tiles of 64
// (3 heads x 4 o-tiles).  Same micro-kernel as kernel 1.
// ---------------------------------------------------------------------------
__global__ void __launch_bounds__(256, 2)
lin_kernel(const float* __restrict__ x, const float* __restrict__ w,
           const float* __restrict__ bias, float* __restrict__ out) {
    __shared__ float sA[128][36];
    __shared__ float sB[32][68];

    const int tid = threadIdx.x;
    const int tx = tid & 15, ty = tid >> 4;
    const int n0 = blockIdx.y * 128;
    const int kblk = blockIdx.x >> 2;          // which of the 3 weight slices
    const int o0 = (blockIdx.x & 3) * 64;      // output-feature tile

    u64 acc[8][2];
#pragma unroll
    for (int r = 0; r < 8; ++r) { acc[r][0] = 0ull; acc[r][1] = 0ull; }

    for (int k0 = 0; k0 < 512; k0 += 32) {
        const float* asrc;
        int coff;
        if (k0 < 256) { asrc = g_x1; coff = k0; }
        else          { asrc = x;    coff = k0 - 256; }

        __syncthreads();
#pragma unroll
        for (int p = 0; p < 4; ++p) {
            int id = tid + p * 256;
            int row = id >> 3, q = id & 7;
            *(float4*)&sA[row][q * 4] =
                *(const float4*)(asrc + (size_t)(n0 + row) * FI + coff + q * 4);
        }
#pragma unroll
        for (int p = 0; p < 2; ++p) {
            int id = tid + p * 256;
            int kk = id >> 4, c4 = id & 15;
            *(float4*)&sB[kk][c4 * 4] =
                *(const float4*)(w + (size_t)kblk * 131072 +
                                 (size_t)(k0 + kk) * 256 + o0 + c4 * 4);
        }
        __syncthreads();

#pragma unroll
        for (int kk = 0; kk < 32; kk += 2) {
            ulonglong2 bA = *(ulonglong2*)&sB[kk][tx * 4];
            ulonglong2 bB = *(ulonglong2*)&sB[kk + 1][tx * 4];
#pragma unroll
            for (int r = 0; r < 8; ++r) {
                float2 a = *(float2*)&sA[ty * 8 + r][kk];
                u64 a0 = dup2(a.x), a1 = dup2(a.y);
                ffma2(acc[r][0], a0, bA.x);
                ffma2(acc[r][1], a0, bA.y);
                ffma2(acc[r][0], a1, bB.x);
                ffma2(acc[r][1], a1, bB.y);
            }
        }
    }

    float4 bv = *(const float4*)(bias + o0 + tx * 4);
#pragma unroll
    for (int r = 0; r < 8; ++r) {
        int row = n0 + ty * 8 + r;
        float2 lo = unpk(acc[r][0]), hi = unpk(acc[r][1]);
        float4 o;
        o.x = lo.x + bv.x; o.y = lo.y + bv.y;
        o.z = hi.x + bv.z; o.w = hi.y + bv.w;
        *(float4*)(out + (size_t)kblk * (NN * 256) + (size_t)row * 256 +
                   o0 + tx * 4) = o;
    }
}

extern "C" void kernel_launch(void* const* d_in, const int* in_sizes, int n_in,
                              void* d_out, int out_size) {
    const float* x = nullptr;
    const int* adj = nullptr;
    const float* w = nullptr;
    const float* bias = nullptr;
    for (int i = 0; i < n_in; ++i) {
        int s = in_sizes[i];
        if (s == NN * NN)           adj  = (const int*)d_in[i];
        else if (s == NN * FI)      x    = (const float*)d_in[i];
        else if (s == 3 * 512 * 256) w   = (const float*)d_in[i];
        else if (s == 256)          bias = (const float*)d_in[i];
        // size-1 input is the unused graph index g
    }
    float* out = (float*)d_out;

    agg_kernel<<<dim3(4, 64), 256>>>(adj, x);
    lin_kernel<<<dim3(12, 64), 256>>>(x, w, bias, out);
}

// round 4
// speedup vs baseline: 2.2143x; 2.2143x over previous
#include <cuda_runtime.h>
#include <cuda_bf16.h>
#include <cstdint>

#define NN 8192
#define FI 256
#define NF (NN * FI)

// ---------------- scratch (device globals; no allocation) ----------------
__device__ float g_x1p[2 * NF];                              // 16 MB k-split partials
__device__ float g_degp[2 * NN];
__device__ __align__(256) __nv_bfloat16 g_xT_hi[FI * NN];    // 4 MB
__device__ __align__(256) __nv_bfloat16 g_xT_lo[FI * NN];    // 4 MB

typedef unsigned long long u64;

// ---------------- PTX helpers (all sm_80-baseline; no tcgen05) ----------------
__device__ __forceinline__ uint32_t smem_u32(const void* p) {
    uint32_t a;
    asm("{ .reg .u64 t; cvta.to.shared.u64 t, %1; cvt.u32.u64 %0, t; }" : "=r"(a) : "l"(p));
    return a;
}
__device__ __forceinline__ void ldsm4(uint32_t& r0, uint32_t& r1, uint32_t& r2,
                                      uint32_t& r3, uint32_t addr) {
    asm volatile("ldmatrix.sync.aligned.m8n8.x4.shared.b16 {%0,%1,%2,%3}, [%4];"
                 : "=r"(r0), "=r"(r1), "=r"(r2), "=r"(r3) : "r"(addr));
}
__device__ __forceinline__ void mma16816(float* d, const uint32_t* a, const uint32_t* b) {
    asm volatile("mma.sync.aligned.m16n8k16.row.col.f32.bf16.bf16.f32 "
                 "{%0,%1,%2,%3}, {%4,%5,%6,%7}, {%8,%9}, {%0,%1,%2,%3};"
                 : "+f"(d[0]), "+f"(d[1]), "+f"(d[2]), "+f"(d[3])
                 : "r"(a[0]), "r"(a[1]), "r"(a[2]), "r"(a[3]), "r"(b[0]), "r"(b[1]));
}
__device__ __forceinline__ void cpasync16(uint32_t dst, const void* src) {
    asm volatile("cp.async.cg.shared.global [%0], [%1], 16;" :: "r"(dst), "l"(src) : "memory");
}
#define CP_COMMIT() asm volatile("cp.async.commit_group;" ::: "memory")
#define CP_WAIT1()  asm volatile("cp.async.wait_group 1;" ::: "memory")
#define CP_WAIT0()  asm volatile("cp.async.wait_group 0;" ::: "memory")

// packed f32x2 helpers (lin kernel)
__device__ __forceinline__ void ffma2(u64& d, u64 a, u64 b) {
    asm("fma.rn.f32x2 %0, %1, %2, %0;" : "+l"(d) : "l"(a), "l"(b));
}
__device__ __forceinline__ u64 dup2(float v) {
    u64 r; asm("mov.b64 %0, {%1, %2};" : "=l"(r) : "f"(v), "f"(v)); return r;
}
__device__ __forceinline__ float2 unpk(u64 v) {
    float2 r; asm("mov.b64 {%0, %1}, %2;" : "=f"(r.x), "=f"(r.y) : "l"(v)); return r;
}

// ---------------------------------------------------------------------------
// Kernel 0: transpose + exact bf16 two-plane split of x:  xT[f][n] = x[n][f]
// ---------------------------------------------------------------------------
__global__ void transpose_split_kernel(const float* __restrict__ x) {
    __shared__ float s[32][33];
    const int tx = threadIdx.x, ty = threadIdx.y;
    const int n0 = blockIdx.x * 32, f0 = blockIdx.y * 32;
#pragma unroll
    for (int i = 0; i < 4; ++i)
        s[ty * 4 + i][tx] = x[(size_t)(n0 + ty * 4 + i) * FI + f0 + tx];
    __syncthreads();
#pragma unroll
    for (int i = 0; i < 4; ++i) {
        const int f = f0 + ty * 4 + i;
        const int n = n0 + tx;
        const float v = s[tx][ty * 4 + i];
        const __nv_bfloat16 h = __float2bfloat16(v);
        g_xT_hi[(size_t)f * NN + n] = h;
        g_xT_lo[(size_t)f * NN + n] = __float2bfloat16(v - __bfloat162float(h));
    }
}

// ---------------------------------------------------------------------------
// Kernel 1: x1 partials = adj @ x  (HMMA bf16, exact two-plane), + degree.
// CTA: M=128 x N=256(all features), K-split 2 via blockIdx.y (K=4096 each).
// 512 threads = 16 warps in 2(m) x 8(n); warp tile 64x32.
// Double-buffered smem: B planes via cp.async, A via LDG->cvt->STS.
// ---------------------------------------------------------------------------
#define KC 32
#define NCH 128                 // 4096 / 32
#define STG_BH 10240            // A: 128 rows * 80B
#define STG_BL 30720            // Bhi: 256 rows * 80B
#define STG_SZ 51200
#define AGG_SMEM (2 * STG_SZ)   // 102400 B

__global__ void __launch_bounds__(512, 1)
agg_hmma_kernel(const int* __restrict__ adj) {
    extern __shared__ char smem[];
    const uint32_t s0 = smem_u32(smem);
    const int tid = threadIdx.x;
    const int lane = tid & 31, wid = tid >> 5;
    const int wm = wid & 1, wn = wid >> 1;     // 2 x 8 warps
    const int m0 = blockIdx.x * 128;
    const int kb = blockIdx.y * 4096;

    // A loader: thread -> (row = tid/4, quarter = tid%4), two int4 per chunk
    const int a_row = tid >> 2, a_q = tid & 3;
    const int* aptr = adj + (size_t)(m0 + a_row) * NN + kb + a_q * 4;
    const uint32_t a_sts = (uint32_t)(a_row * 80 + a_q * 8);

    // B loader: thread -> (plane = tid/256, feature row = tid%256), 4x16B per chunk
    const int b_pl = tid >> 8, b_row = tid & 255;
    const __nv_bfloat16* bsrc = (b_pl ? g_xT_lo : g_xT_hi) + (size_t)b_row * NN + kb;
    const uint32_t b_sts = (b_pl ? STG_BL : STG_BH) + (uint32_t)(b_row * 80);

    // ldmatrix per-lane invariant offsets
    const uint32_t a_off =
        (uint32_t)((wm * 64 + (lane & 7) + ((lane >> 3) & 1) * 8) * 80 + ((lane >> 4) & 1) * 16);
    const uint32_t b_off =
        (uint32_t)((wn * 32 + (lane & 7) + ((lane >> 4) & 1) * 8) * 80 + ((lane >> 3) & 1) * 16);

    float acc[4][4][4];
#pragma unroll
    for (int i = 0; i < 4; ++i)
#pragma unroll
        for (int j = 0; j < 4; ++j)
#pragma unroll
            for (int q = 0; q < 4; ++q) acc[i][j][q] = 0.f;
    int deg = 0;

    // ---- prologue: chunk 0 ----
    int4 pu = *(const int4*)(aptr);
    int4 pv = *(const int4*)(aptr + 16);
    {
        const uint32_t stg = s0;
#pragma unroll
        for (int cc = 0; cc < 4; ++cc)
            cpasync16(stg + b_sts + cc * 16, bsrc + cc * 8);
        CP_COMMIT();
        deg += pu.x + pu.y + pu.z + pu.w + pv.x + pv.y + pv.z + pv.w;
        uint32_t p0 = (pu.x ? 0x3F80u : 0u) | (pu.y ? 0x3F800000u : 0u);
        uint32_t p1 = (pu.z ? 0x3F80u : 0u) | (pu.w ? 0x3F800000u : 0u);
        uint32_t p2 = (pv.x ? 0x3F80u : 0u) | (pv.y ? 0x3F800000u : 0u);
        uint32_t p3 = (pv.z ? 0x3F80u : 0u) | (pv.w ? 0x3F800000u : 0u);
        asm volatile("st.shared.v2.b32 [%0], {%1,%2};" :: "r"(stg + a_sts), "r"(p0), "r"(p1) : "memory");
        asm volatile("st.shared.v2.b32 [%0], {%1,%2};" :: "r"(stg + a_sts + 32), "r"(p2), "r"(p3) : "memory");
    }

    for (int c = 0; c < NCH; ++c) {
        const uint32_t cur = s0 + (uint32_t)(c & 1) * STG_SZ;
        const uint32_t nxt = s0 + (uint32_t)((c + 1) & 1) * STG_SZ;
        const bool more = (c + 1 < NCH);
        int4 u, v;
        if (more) {
            u = *(const int4*)(aptr + (size_t)(c + 1) * KC);
            v = *(const int4*)(aptr + (size_t)(c + 1) * KC + 16);
#pragma unroll
            for (int cc = 0; cc < 4; ++cc)
                cpasync16(nxt + b_sts + cc * 16, bsrc + (size_t)(c + 1) * KC + cc * 8);
            CP_COMMIT();
            CP_WAIT1();
        } else {
            CP_WAIT0();
        }
        __syncthreads();

        // ---- compute on cur ----
        const uint32_t aB = cur + a_off;
        const uint32_t bhB = cur + STG_BH + b_off;
        const uint32_t blB = cur + STG_BL + b_off;
#pragma unroll
        for (int ks = 0; ks < 2; ++ks) {
            uint32_t a[4][4];
#pragma unroll
            for (int mt = 0; mt < 4; ++mt)
                ldsm4(a[mt][0], a[mt][1], a[mt][2], a[mt][3], aB + mt * 1280 + ks * 32);
            uint32_t bh[2][4];
#pragma unroll
            for (int p2 = 0; p2 < 2; ++p2)
                ldsm4(bh[p2][0], bh[p2][1], bh[p2][2], bh[p2][3], bhB + p2 * 1280 + ks * 32);
#pragma unroll
            for (int mt = 0; mt < 4; ++mt)
#pragma unroll
                for (int nt = 0; nt < 4; ++nt)
                    mma16816(acc[mt][nt], a[mt], &bh[nt >> 1][(nt & 1) * 2]);
            uint32_t bl[2][4];
#pragma unroll
            for (int p2 = 0; p2 < 2; ++p2)
                ldsm4(bl[p2][0], bl[p2][1], bl[p2][2], bl[p2][3], blB + p2 * 1280 + ks * 32);
#pragma unroll
            for (int mt = 0; mt < 4; ++mt)
#pragma unroll
                for (int nt = 0; nt < 4; ++nt)
                    mma16816(acc[mt][nt], a[mt], &bl[nt >> 1][(nt & 1) * 2]);
        }

        if (more) {
            deg += u.x + u.y + u.z + u.w + v.x + v.y + v.z + v.w;
            uint32_t p0 = (u.x ? 0x3F80u : 0u) | (u.y ? 0x3F800000u : 0u);
            uint32_t p1 = (u.z ? 0x3F80u : 0u) | (u.w ? 0x3F800000u : 0u);
            uint32_t p2 = (v.x ? 0x3F80u : 0u) | (v.y ? 0x3F800000u : 0u);
            uint32_t p3 = (v.z ? 0x3F80u : 0u) | (v.w ? 0x3F800000u : 0u);
            asm volatile("st.shared.v2.b32 [%0], {%1,%2};" :: "r"(nxt + a_sts), "r"(p0), "r"(p1) : "memory");
            asm volatile("st.shared.v2.b32 [%0], {%1,%2};" :: "r"(nxt + a_sts + 32), "r"(p2), "r"(p3) : "memory");
        }
        __syncthreads();
    }

    // degree: reduce 4 lanes per row, write partial
    deg += __shfl_xor_sync(0xFFFFFFFFu, deg, 1);
    deg += __shfl_xor_sync(0xFFFFFFFFu, deg, 2);
    if ((lane & 3) == 0)
        g_degp[blockIdx.y * NN + m0 + a_row] = (float)deg;

    // write accumulator partials
    float* outp = g_x1p + (size_t)blockIdx.y * NF;
#pragma unroll
    for (int mt = 0; mt < 4; ++mt) {
        const int r0 = m0 + wm * 64 + mt * 16 + (lane >> 2);
#pragma unroll
        for (int nt = 0; nt < 4; ++nt) {
            const int cc = wn * 32 + nt * 8 + (lane & 3) * 2;
            *(float2*)(outp + (size_t)r0 * FI + cc) =
                make_float2(acc[mt][nt][0], acc[mt][nt][1]);
            *(float2*)(outp + (size_t)(r0 + 8) * FI + cc) =
                make_float2(acc[mt][nt][2], acc[mt][nt][3]);
        }
    }
}

// ---------------------------------------------------------------------------
// Kernel 2: out[k, n, o] = [x1|x][n, :] @ W[k] + bias   (FFMA2 path)
// x1 assembled on the fly: (part0 + part1) * (1/deg)
// ---------------------------------------------------------------------------
__global__ void __launch_bounds__(256, 2)
lin_kernel(const float* __restrict__ x, const float* __restrict__ w,
           const float* __restrict__ bias, float* __restrict__ out) {
    __shared__ float sA[128][36];
    __shared__ float sB[32][68];

    const int tid = threadIdx.x;
    const int tx = tid & 15, ty = tid >> 4;
    const int n0 = blockIdx.y * 128;
    const int kblk = blockIdx.x >> 2;
    const int o0 = (blockIdx.x & 3) * 64;

    // hoisted reciprocal degrees for the 4 rows this thread loads
    float invp[4];
#pragma unroll
    for (int p = 0; p < 4; ++p) {
        const int row = (tid + p * 256) >> 3;
        invp[p] = 1.0f / (g_degp[n0 + row] + g_degp[NN + n0 + row]);
    }

    u64 acc[8][2];
#pragma unroll
    for (int r = 0; r < 8; ++r) { acc[r][0] = 0ull; acc[r][1] = 0ull; }

    for (int k0 = 0; k0 < 512; k0 += 32) {
        __syncthreads();
        if (k0 < 256) {
#pragma unroll
            for (int p = 0; p < 4; ++p) {
                const int id = tid + p * 256;
                const int row = id >> 3, q = id & 7;
                const size_t idx = (size_t)(n0 + row) * FI + k0 + q * 4;
                const float4 a0 = *(const float4*)(g_x1p + idx);
                const float4 a1 = *(const float4*)(g_x1p + NF + idx);
                float4 r;
                r.x = (a0.x + a1.x) * invp[p];
                r.y = (a0.y + a1.y) * invp[p];
                r.z = (a0.z + a1.z) * invp[p];
                r.w = (a0.w + a1.w) * invp[p];
                *(float4*)&sA[row][q * 4] = r;
            }
        } else {
#pragma unroll
            for (int p = 0; p < 4; ++p) {
                const int id = tid + p * 256;
                const int row = id >> 3, q = id & 7;
                *(float4*)&sA[row][q * 4] =
                    *(const float4*)(x + (size_t)(n0 + row) * FI + (k0 - 256) + q * 4);
            }
        }
#pragma unroll
        for (int p = 0; p < 2; ++p) {
            const int id = tid + p * 256;
            const int kk = id >> 4, c4 = id & 15;
            *(float4*)&sB[kk][c4 * 4] =
                *(const float4*)(w + (size_t)kblk * 131072 +
                                 (size_t)(k0 + kk) * 256 + o0 + c4 * 4);
        }
        __syncthreads();

#pragma unroll
        for (int kk = 0; kk < 32; kk += 2) {
            ulonglong2 bA = *(ulonglong2*)&sB[kk][tx * 4];
            ulonglong2 bB = *(ulonglong2*)&sB[kk + 1][tx * 4];
#pragma unroll
            for (int r = 0; r < 8; ++r) {
                float2 a = *(float2*)&sA[ty * 8 + r][kk];
                u64 a0 = dup2(a.x), a1 = dup2(a.y);
                ffma2(acc[r][0], a0, bA.x);
                ffma2(acc[r][1], a0, bA.y);
                ffma2(acc[r][0], a1, bB.x);
                ffma2(acc[r][1], a1, bB.y);
            }
        }
    }

    float4 bv = *(const float4*)(bias + o0 + tx * 4);
#pragma unroll
    for (int r = 0; r < 8; ++r) {
        const int row = n0 + ty * 8 + r;
        float2 lo = unpk(acc[r][0]), hi = unpk(acc[r][1]);
        float4 o;
        o.x = lo.x + bv.x; o.y = lo.y + bv.y;
        o.z = hi.x + bv.z; o.w = hi.y + bv.w;
        *(float4*)(out + (size_t)kblk * (NN * 256) + (size_t)row * 256 +
                   o0 + tx * 4) = o;
    }
}

extern "C" void kernel_launch(void* const* d_in, const int* in_sizes, int n_in,
                              void* d_out, int out_size) {
    const float* x = nullptr;
    const int* adj = nullptr;
    const float* w = nullptr;
    const float* bias = nullptr;
    for (int i = 0; i < n_in; ++i) {
        int s = in_sizes[i];
        if (s == NN * NN)            adj  = (const int*)d_in[i];
        else if (s == NN * FI)       x    = (const float*)d_in[i];
        else if (s == 3 * 512 * 256) w    = (const float*)d_in[i];
        else if (s == 256)           bias = (const float*)d_in[i];
    }
    float* out = (float*)d_out;

    static bool attr_done = false;
    if (!attr_done) {
        cudaFuncSetAttribute(agg_hmma_kernel,
                             cudaFuncAttributeMaxDynamicSharedMemorySize, AGG_SMEM);
        attr_done = true;
    }

    transpose_split_kernel<<<dim3(NN / 32, FI / 32), dim3(32, 8)>>>(x);
    agg_hmma_kernel<<<dim3(64, 2), 512, AGG_SMEM>>>(adj);
    lin_kernel<<<dim3(12, 64), 256>>>(x, w, bias, out);
}

// round 5
// speedup vs baseline: 3.4856x; 1.5741x over previous
#include <cuda_runtime.h>
#include <cuda_bf16.h>
#include <cstdint>

#define NN 8192
#define FI 256
#define NF (NN * FI)

// ---------------- scratch (device globals; no allocation) ----------------
__device__ __align__(16) __nv_bfloat16 g_xT_hi[FI * NN];   // x^T, bf16 hi (agg B)
__device__ __align__(16) __nv_bfloat16 g_x_hi[NF];         // x row-major hi  (lin A)
__device__ __align__(16) __nv_bfloat16 g_x_lo[NF];         // x row-major lo  (lin A)
__device__ __align__(16) __nv_bfloat16 g_x1_hi[NF];        // x1 row-major hi (lin A)
__device__ __align__(16) __nv_bfloat16 g_x1_lo[NF];        // x1 row-major lo (lin A)
__device__ __align__(16) __nv_bfloat16 g_Wt_hi[3 * FI * 512];  // W^T hi (lin B)
__device__ __align__(16) __nv_bfloat16 g_Wt_lo[3 * FI * 512];  // W^T lo (lin B)

// ---------------- PTX helpers ----------------
__device__ __forceinline__ uint32_t smem_u32(const void* p) {
    uint32_t a;
    asm("{ .reg .u64 t; cvta.to.shared.u64 t, %1; cvt.u32.u64 %0, t; }" : "=r"(a) : "l"(p));
    return a;
}
__device__ __forceinline__ void ldsm4(uint32_t& r0, uint32_t& r1, uint32_t& r2,
                                      uint32_t& r3, uint32_t addr) {
    asm volatile("ldmatrix.sync.aligned.m8n8.x4.shared.b16 {%0,%1,%2,%3}, [%4];"
                 : "=r"(r0), "=r"(r1), "=r"(r2), "=r"(r3) : "r"(addr));
}
__device__ __forceinline__ void mma16816(float* d, const uint32_t* a, const uint32_t* b) {
    asm volatile("mma.sync.aligned.m16n8k16.row.col.f32.bf16.bf16.f32 "
                 "{%0,%1,%2,%3}, {%4,%5,%6,%7}, {%8,%9}, {%0,%1,%2,%3};"
                 : "+f"(d[0]), "+f"(d[1]), "+f"(d[2]), "+f"(d[3])
                 : "r"(a[0]), "r"(a[1]), "r"(a[2]), "r"(a[3]), "r"(b[0]), "r"(b[1]));
}
__device__ __forceinline__ void cpasync16(uint32_t dst, const void* src) {
    asm volatile("cp.async.cg.shared.global [%0], [%1], 16;" :: "r"(dst), "l"(src) : "memory");
}
#define CP_COMMIT() asm volatile("cp.async.commit_group;" ::: "memory")
#define CP_WAIT1()  asm volatile("cp.async.wait_group 1;" ::: "memory")
#define CP_WAIT0()  asm volatile("cp.async.wait_group 0;" ::: "memory")

__device__ __forceinline__ void split_store(__nv_bfloat16* hi, __nv_bfloat16* lo,
                                            float v0, float v1) {
    __nv_bfloat16 h0 = __float2bfloat16(v0), h1 = __float2bfloat16(v1);
    __nv_bfloat16 l0 = __float2bfloat16(v0 - __bfloat162float(h0));
    __nv_bfloat16 l1 = __float2bfloat16(v1 - __bfloat162float(h1));
    *(__nv_bfloat162*)hi = __nv_bfloat162(h0, h1);
    *(__nv_bfloat162*)lo = __nv_bfloat162(l0, l1);
}

// ---------------------------------------------------------------------------
// Prep 1: x -> row-major hi/lo planes + transposed hi plane
// ---------------------------------------------------------------------------
__global__ void xprep_kernel(const float* __restrict__ x) {
    __shared__ float s[32][33];
    const int tx = threadIdx.x, ty = threadIdx.y;
    const int n0 = blockIdx.x * 32, f0 = blockIdx.y * 32;
#pragma unroll
    for (int i = 0; i < 4; ++i) {
        const int n = n0 + ty * 4 + i, f = f0 + tx;
        const float v = x[(size_t)n * FI + f];
        s[ty * 4 + i][tx] = v;
        const __nv_bfloat16 h = __float2bfloat16(v);
        g_x_hi[(size_t)n * FI + f] = h;
        g_x_lo[(size_t)n * FI + f] = __float2bfloat16(v - __bfloat162float(h));
    }
    __syncthreads();
#pragma unroll
    for (int i = 0; i < 4; ++i) {
        const int f = f0 + ty * 4 + i, n = n0 + tx;
        g_xT_hi[(size_t)f * NN + n] = __float2bfloat16(s[tx][ty * 4 + i]);
    }
}

// ---------------------------------------------------------------------------
// Prep 2: W[3][512][256] -> W^T hi/lo [3][256 o][512 k]
// ---------------------------------------------------------------------------
__global__ void wprep_kernel(const float* __restrict__ w) {
    __shared__ float s[32][33];
    const int tx = threadIdx.x, ty = threadIdx.y;
    const int k0 = blockIdx.x * 32, o0 = blockIdx.y * 32, h = blockIdx.z;
#pragma unroll
    for (int i = 0; i < 4; ++i)
        s[ty * 4 + i][tx] = w[(size_t)h * 512 * 256 + (size_t)(k0 + ty * 4 + i) * 256 + o0 + tx];
    __syncthreads();
#pragma unroll
    for (int i = 0; i < 4; ++i) {
        const int o = o0 + ty * 4 + i, k = k0 + tx;
        const float v = s[tx][ty * 4 + i];
        const __nv_bfloat16 hh = __float2bfloat16(v);
        const size_t idx = (size_t)h * FI * 512 + (size_t)o * 512 + k;
        g_Wt_hi[idx] = hh;
        g_Wt_lo[idx] = __float2bfloat16(v - __bfloat162float(hh));
    }
}

// ---------------------------------------------------------------------------
// Kernel 1: x1 = (adj @ x_hi) / deg — single-plane bf16 HMMA, full K per CTA.
// CTA tile M=64 x N=256, 512 threads = 16 warps (2m x 8n), warp 32x32.
// KC=64 chunks, double-buffered; epilogue emits x1 hi/lo bf16 planes.
// ---------------------------------------------------------------------------
#define KC 64
#define ANCH (NN / KC)            // 128
#define AROWB 144                 // padded row stride (bytes)
#define A_B_OFF (64 * AROWB)      // 9216
#define ASTG (A_B_OFF + 256 * AROWB)   // 46080
#define AGG_SMEM (2 * ASTG)       // 92160

__global__ void __launch_bounds__(512, 1)
agg_hmma_kernel(const int* __restrict__ adj) {
    extern __shared__ char smem[];
    __shared__ float sInv[64];
    const uint32_t s0 = smem_u32(smem);
    const int tid = threadIdx.x;
    const int lane = tid & 31, wid = tid >> 5;
    const int wm = wid & 1, wn = wid >> 1;
    const int m0 = blockIdx.x * 64;

    // A loader: 64 rows, 8 threads/row, 2 int4 each per chunk
    const int a_row = tid >> 3, a_q = tid & 7;
    const int* aptr = adj + (size_t)(m0 + a_row) * NN + a_q * 4;
    const uint32_t a_sts = (uint32_t)(a_row * AROWB + a_q * 8);

    // B loader: 256 feature rows, 2 threads/row, 4x16B each per chunk
    const int b_row = tid >> 1, b_half = tid & 1;
    const __nv_bfloat16* bsrc = g_xT_hi + (size_t)b_row * NN + b_half * 32;
    const uint32_t b_sts = A_B_OFF + (uint32_t)(b_row * AROWB + b_half * 64);

    const uint32_t a_off =
        (uint32_t)((wm * 32 + (lane & 7) + ((lane >> 3) & 1) * 8) * AROWB + ((lane >> 4) & 1) * 16);
    const uint32_t b_off =
        (uint32_t)((wn * 32 + (lane & 7) + ((lane >> 4) & 1) * 8) * AROWB + ((lane >> 3) & 1) * 16);

    float acc[2][4][4];
#pragma unroll
    for (int i = 0; i < 2; ++i)
#pragma unroll
        for (int j = 0; j < 4; ++j)
#pragma unroll
            for (int q = 0; q < 4; ++q) acc[i][j][q] = 0.f;
    int deg = 0;

    // prologue: chunk 0
    int4 pu = *(const int4*)(aptr);
    int4 pv = *(const int4*)(aptr + 32);
    {
#pragma unroll
        for (int cc = 0; cc < 4; ++cc)
            cpasync16(s0 + b_sts + cc * 16, bsrc + cc * 8);
        CP_COMMIT();
        deg += pu.x + pu.y + pu.z + pu.w + pv.x + pv.y + pv.z + pv.w;
        uint32_t p0 = (pu.x ? 0x3F80u : 0u) | (pu.y ? 0x3F800000u : 0u);
        uint32_t p1 = (pu.z ? 0x3F80u : 0u) | (pu.w ? 0x3F800000u : 0u);
        uint32_t p2 = (pv.x ? 0x3F80u : 0u) | (pv.y ? 0x3F800000u : 0u);
        uint32_t p3 = (pv.z ? 0x3F80u : 0u) | (pv.w ? 0x3F800000u : 0u);
        asm volatile("st.shared.v2.b32 [%0], {%1,%2};" :: "r"(s0 + a_sts), "r"(p0), "r"(p1) : "memory");
        asm volatile("st.shared.v2.b32 [%0], {%1,%2};" :: "r"(s0 + a_sts + 64), "r"(p2), "r"(p3) : "memory");
    }

    for (int c = 0; c < ANCH; ++c) {
        const uint32_t cur = s0 + (uint32_t)(c & 1) * ASTG;
        const uint32_t nxt = s0 + (uint32_t)((c + 1) & 1) * ASTG;
        const bool more = (c + 1 < ANCH);
        int4 u, v;
        if (more) {
            u = *(const int4*)(aptr + (size_t)(c + 1) * KC);
            v = *(const int4*)(aptr + (size_t)(c + 1) * KC + 32);
#pragma unroll
            for (int cc = 0; cc < 4; ++cc)
                cpasync16(nxt + b_sts + cc * 16, bsrc + (size_t)(c + 1) * KC + cc * 8);
            CP_COMMIT();
            CP_WAIT1();
        } else {
            CP_WAIT0();
        }
        __syncthreads();

        const uint32_t aB = cur + a_off;
        const uint32_t bB = cur + A_B_OFF + b_off;
#pragma unroll
        for (int ks = 0; ks < 4; ++ks) {
            uint32_t a[2][4], b[2][4];
#pragma unroll
            for (int mt = 0; mt < 2; ++mt)
                ldsm4(a[mt][0], a[mt][1], a[mt][2], a[mt][3], aB + mt * (16 * AROWB) + ks * 32);
#pragma unroll
            for (int p2 = 0; p2 < 2; ++p2)
                ldsm4(b[p2][0], b[p2][1], b[p2][2], b[p2][3], bB + p2 * (16 * AROWB) + ks * 32);
#pragma unroll
            for (int mt = 0; mt < 2; ++mt)
#pragma unroll
                for (int nt = 0; nt < 4; ++nt)
                    mma16816(acc[mt][nt], a[mt], &b[nt >> 1][(nt & 1) * 2]);
        }

        if (more) {
            deg += u.x + u.y + u.z + u.w + v.x + v.y + v.z + v.w;
            uint32_t p0 = (u.x ? 0x3F80u : 0u) | (u.y ? 0x3F800000u : 0u);
            uint32_t p1 = (u.z ? 0x3F80u : 0u) | (u.w ? 0x3F800000u : 0u);
            uint32_t p2 = (v.x ? 0x3F80u : 0u) | (v.y ? 0x3F800000u : 0u);
            uint32_t p3 = (v.z ? 0x3F80u : 0u) | (v.w ? 0x3F800000u : 0u);
            asm volatile("st.shared.v2.b32 [%0], {%1,%2};" :: "r"(nxt + a_sts), "r"(p0), "r"(p1) : "memory");
            asm volatile("st.shared.v2.b32 [%0], {%1,%2};" :: "r"(nxt + a_sts + 64), "r"(p2), "r"(p3) : "memory");
        }
        __syncthreads();
    }

    // degree reduce (8 lanes per row)
    deg += __shfl_xor_sync(0xFFFFFFFFu, deg, 1);
    deg += __shfl_xor_sync(0xFFFFFFFFu, deg, 2);
    deg += __shfl_xor_sync(0xFFFFFFFFu, deg, 4);
    if ((tid & 7) == 0) sInv[tid >> 3] = 1.0f / (float)deg;
    __syncthreads();

    // epilogue: x1 -> bf16 hi/lo planes
#pragma unroll
    for (int mt = 0; mt < 2; ++mt) {
        const int r = wm * 32 + mt * 16 + (lane >> 2);
        const float inv0 = sInv[r], inv1 = sInv[r + 8];
#pragma unroll
        for (int nt = 0; nt < 4; ++nt) {
            const int cc = wn * 32 + nt * 8 + (lane & 3) * 2;
            const size_t i0 = (size_t)(m0 + r) * FI + cc;
            const size_t i1 = (size_t)(m0 + r + 8) * FI + cc;
            split_store(g_x1_hi + i0, g_x1_lo + i0,
                        acc[mt][nt][0] * inv0, acc[mt][nt][1] * inv0);
            split_store(g_x1_hi + i1, g_x1_lo + i1,
                        acc[mt][nt][2] * inv1, acc[mt][nt][3] * inv1);
        }
    }
}

// ---------------------------------------------------------------------------
// Kernel 2: out[k] = [x1|x] @ W[k] + bias via HMMA, two-plane (drop lo*lo).
// Effective K = 1536: [Ahi|Alo|Ahi] x [Whi;Whi;Wlo].
// CTA M=128 x N=128 (o-tile), 512 threads = 16 warps (4m x 4n), warp 32x32.
// ---------------------------------------------------------------------------
#define LKC 32
#define LNCH 48
#define LROWB 80
#define L_B_OFF (128 * LROWB)     // 10240
#define LSTG (2 * 128 * LROWB)    // 20480
#define LIN_SMEM (2 * LSTG)       // 40960

__global__ void __launch_bounds__(512, 1)
lin_hmma_kernel(const float* __restrict__ bias, float* __restrict__ out) {
    extern __shared__ char smem[];
    const uint32_t s0 = smem_u32(smem);
    const int tid = threadIdx.x;
    const int lane = tid & 31, wid = tid >> 5;
    const int wm = wid & 3, wn = wid >> 2;
    const int n0 = blockIdx.y * 128;
    const int head = blockIdx.x >> 1;
    const int o0 = (blockIdx.x & 1) * 128;

    const int ar = tid >> 2, aq = tid & 3;       // A: 128 rows, 4 thr/row
    const uint32_t a_sts = (uint32_t)(ar * LROWB + aq * 16);
    const uint32_t b_sts = L_B_OFF + a_sts;

    const uint32_t a_off =
        (uint32_t)((wm * 32 + (lane & 7) + ((lane >> 3) & 1) * 8) * LROWB + ((lane >> 4) & 1) * 16);
    const uint32_t b_off =
        (uint32_t)((wn * 32 + (lane & 7) + ((lane >> 4) & 1) * 8) * LROWB + ((lane >> 3) & 1) * 16);

    float acc[2][4][4];
#pragma unroll
    for (int i = 0; i < 2; ++i)
#pragma unroll
        for (int j = 0; j < 4; ++j)
#pragma unroll
            for (int q = 0; q < 4; ++q) acc[i][j][q] = 0.f;

    auto issue = [&](int c, uint32_t stg) {
        const int gk = c * LKC;
        const int seg = gk >> 9;            // 0,1,2
        const int kk = gk & 511;
        const __nv_bfloat16* asrc;
        if (seg == 1) asrc = (kk & 256) ? g_x_lo : g_x1_lo;
        else          asrc = (kk & 256) ? g_x_hi : g_x1_hi;
        const int col = kk & 255;
        cpasync16(stg + a_sts, asrc + (size_t)(n0 + ar) * FI + col + aq * 8);
        const __nv_bfloat16* bsrc = (seg == 2 ? g_Wt_lo : g_Wt_hi) +
            (size_t)head * FI * 512 + (size_t)(o0 + ar) * 512 + kk + aq * 8;
        cpasync16(stg + b_sts, bsrc);
        CP_COMMIT();
    };

    issue(0, s0);

    for (int c = 0; c < LNCH; ++c) {
        const uint32_t cur = s0 + (uint32_t)(c & 1) * LSTG;
        const uint32_t nxt = s0 + (uint32_t)((c + 1) & 1) * LSTG;
        const bool more = (c + 1 < LNCH);
        if (more) { issue(c + 1, nxt); CP_WAIT1(); }
        else      { CP_WAIT0(); }
        __syncthreads();

        const uint32_t aB = cur + a_off;
        const uint32_t bB = cur + L_B_OFF + b_off;
#pragma unroll
        for (int ks = 0; ks < 2; ++ks) {
            uint32_t a[2][4], b[2][4];
#pragma unroll
            for (int mt = 0; mt < 2; ++mt)
                ldsm4(a[mt][0], a[mt][1], a[mt][2], a[mt][3], aB + mt * (16 * LROWB) + ks * 32);
#pragma unroll
            for (int p2 = 0; p2 < 2; ++p2)
                ldsm4(b[p2][0], b[p2][1], b[p2][2], b[p2][3], bB + p2 * (16 * LROWB) + ks * 32);
#pragma unroll
            for (int mt = 0; mt < 2; ++mt)
#pragma unroll
                for (int nt = 0; nt < 4; ++nt)
                    mma16816(acc[mt][nt], a[mt], &b[nt >> 1][(nt & 1) * 2]);
        }
        __syncthreads();
    }

    float* obase = out + (size_t)head * NN * FI;
#pragma unroll
    for (int mt = 0; mt < 2; ++mt) {
        const int r = n0 + wm * 32 + mt * 16 + (lane >> 2);
#pragma unroll
        for (int nt = 0; nt < 4; ++nt) {
            const int c = o0 + wn * 32 + nt * 8 + (lane & 3) * 2;
            const float b0 = __ldg(bias + c), b1 = __ldg(bias + c + 1);
            *(float2*)(obase + (size_t)r * FI + c) =
                make_float2(acc[mt][nt][0] + b0, acc[mt][nt][1] + b1);
            *(float2*)(obase + (size_t)(r + 8) * FI + c) =
                make_float2(acc[mt][nt][2] + b0, acc[mt][nt][3] + b1);
        }
    }
}

extern "C" void kernel_launch(void* const* d_in, const int* in_sizes, int n_in,
                              void* d_out, int out_size) {
    const float* x = nullptr;
    const int* adj = nullptr;
    const float* w = nullptr;
    const float* bias = nullptr;
    for (int i = 0; i < n_in; ++i) {
        int s = in_sizes[i];
        if (s == NN * NN)            adj  = (const int*)d_in[i];
        else if (s == NN * FI)       x    = (const float*)d_in[i];
        else if (s == 3 * 512 * 256) w    = (const float*)d_in[i];
        else if (s == 256)           bias = (const float*)d_in[i];
    }
    float* out = (float*)d_out;

    static bool attr_done = false;
    if (!attr_done) {
        cudaFuncSetAttribute(agg_hmma_kernel,
                             cudaFuncAttributeMaxDynamicSharedMemorySize, AGG_SMEM);
        cudaFuncSetAttribute(lin_hmma_kernel,
                             cudaFuncAttributeMaxDynamicSharedMemorySize, LIN_SMEM);
        attr_done = true;
    }

    xprep_kernel<<<dim3(NN / 32, FI / 32), dim3(32, 8)>>>(x);
    wprep_kernel<<<dim3(16, 8, 3), dim3(32, 8)>>>(w);
    agg_hmma_kernel<<<128, 512, AGG_SMEM>>>(adj);
    lin_hmma_kernel<<<dim3(6, 64), 512, LIN_SMEM>>>(bias, out);
}